// round 2
// baseline (speedup 1.0000x reference)
#include <cuda_runtime.h>

typedef unsigned long long u64;

#define B_    1024
#define C_    200
#define HW_   225
#define F_    12
#define FR_   6
#define NELEM (C_*HW_)   /* 45000 */

// ---------------- scratch (static device arrays; no allocation) -------------
__device__ float g_kqs[B_*HW_];   // kqs[b][n]
__device__ float g_pp [B_*C_];    // p[b][c] - mean_c(p[b])
__device__ float g_sc [B_*2];     // {Vp, Cpd} per batch

// ---------------- packed-f32 helpers ---------------------------------------
__device__ __forceinline__ u64 pk2(float lo, float hi){
    u64 r; asm("mov.b64 %0, {%1,%2};" : "=l"(r) : "f"(lo), "f"(hi)); return r;
}
__device__ __forceinline__ void upk2(u64 v, float &lo, float &hi){
    asm("mov.b64 {%0,%1}, %2;" : "=f"(lo), "=f"(hi) : "l"(v));
}
__device__ __forceinline__ u64 fma2(u64 a, u64 b, u64 c){
    u64 d; asm("fma.rn.f32x2 %0, %1, %2, %3;" : "=l"(d) : "l"(a), "l"(b), "l"(c));
    return d;
}

// ============================================================================
// K1: per-batch block. GEMM k/q/v -> kqs[n], vm -> softmax -> u -> p[c],
// plus per-batch LN scalar prep (Vp, Cpd).
// ============================================================================
__global__ __launch_bounds__(256, 2) void k1_kernel(
    const float* __restrict__ X,
    const float* __restrict__ w11, const float* __restrict__ b11,
    const float* __restrict__ w21, const float* __restrict__ b21,
    const float* __restrict__ w31, const float* __restrict__ b31,
    const float* __restrict__ w41, const float* __restrict__ b41,
    const float* __restrict__ w42, const float* __restrict__ b42)
{
    __shared__ __align__(16) u64 wpk[C_][20];   // 18 used: k0..5,q0..5,v0..5 pairs
    __shared__ float v_s[F_][HW_+7];            // 12 x 232
    __shared__ float vm_s[F_], vs_s[F_], u_s[FR_];
    __shared__ float wred[8][4];
    __shared__ float tot[4];

    const int tid = threadIdx.x;
    const int b   = blockIdx.x;

    // ---- pack weights into smem: wpk[c][j] = (w[2j][c], w[2j+1][c]) --------
    for (int idx = tid; idx < C_*18; idx += 256){
        int c = idx/18, j = idx%18;
        int role = j/6, jj = j%6;
        const float* w = (role==0) ? w11 : (role==1) ? w21 : w31;
        wpk[c][j] = pk2(w[(2*jj)*C_ + c], w[(2*jj+1)*C_ + c]);
    }
    __syncthreads();

    // ---- GEMM: thread owns one spatial column n ----------------------------
    const int n = (tid < HW_) ? tid : (HW_-1);
    const float* xp = X + (size_t)b*NELEM + n;

    u64 acc[18];
    #pragma unroll
    for (int j=0;j<18;j++) acc[j] = 0ULL;

    #pragma unroll 2
    for (int c=0;c<C_;c++){
        float x = xp[c*HW_];
        u64 xx = pk2(x, x);
        const u64* wr = wpk[c];
        #pragma unroll
        for (int m=0;m<9;m++){
            ulonglong2 w2 = *reinterpret_cast<const ulonglong2*>(wr + 2*m);
            acc[2*m]   = fma2(w2.x, xx, acc[2*m]);
            acc[2*m+1] = fma2(w2.y, xx, acc[2*m+1]);
        }
    }

    // ---- epilogue: biases, kqs, store v ------------------------------------
    if (tid < HW_){
        float kv[12], qv[12], vv[12];
        #pragma unroll
        for (int j=0;j<6;j++){
            upk2(acc[j],     kv[2*j], kv[2*j+1]);
            upk2(acc[6+j],   qv[2*j], qv[2*j+1]);
            upk2(acc[12+j],  vv[2*j], vv[2*j+1]);
        }
        float kqs = 0.f;
        #pragma unroll
        for (int f=0; f<12; f++){
            float kf = kv[f] + b11[f];
            float qf = qv[f] + b21[f];
            kqs = fmaf(kf, qf, kqs);
            v_s[f][n] = vv[f] + b31[f];
        }
        g_kqs[b*HW_ + n] = kqs;
    }
    __syncthreads();

    // ---- vm: scrambled-reshape mean (matches reference raw reshape) --------
    if (tid < F_){
        int j = tid;
        float s = 0.f;
        for (int m=0;m<HW_;m++){
            int flat = j*HW_ + m;
            int fc   = flat % 12;
            int r180 = flat % 180;
            int nn   = (flat/180)*15 + (r180/12);
            s += v_s[fc][nn];
        }
        vm_s[j] = s * (1.0f/HW_);
    }
    __syncthreads();

    // ---- softmax over f=12 (thread 0) --------------------------------------
    if (tid == 0){
        float mx = vm_s[0];
        #pragma unroll
        for (int j=1;j<12;j++) mx = fmaxf(mx, vm_s[j]);
        float e[12], ssum = 0.f;
        #pragma unroll
        for (int j=0;j<12;j++){ e[j] = __expf(vm_s[j]-mx); ssum += e[j]; }
        float inv = 1.0f/ssum;
        #pragma unroll
        for (int j=0;j<12;j++) vs_s[j] = e[j]*inv;
    }
    __syncthreads();

    // ---- u[i] = sum_l vs[l] * w41[i,l] -------------------------------------
    if (tid < FR_){
        float u = 0.f;
        #pragma unroll
        for (int l=0;l<12;l++) u = fmaf(vs_s[l], w41[tid*12+l], u);
        u_s[tid] = u;
    }
    __syncthreads();

    // ---- p[c], d[c] and deterministic reductions ---------------------------
    float p = 0.f, d = 0.f;
    if (tid < C_){
        #pragma unroll
        for (int i=0;i<6;i++){
            float wv = w42[tid*6+i];
            p = fmaf(u_s[i],  wv, p);
            d = fmaf(b41[i],  wv, d);
        }
        d += b42[tid];
    }
    float s0 = p, s1 = p*p, s2 = p*d, s3 = d;
    #pragma unroll
    for (int o=16;o>0;o>>=1){
        s0 += __shfl_down_sync(0xffffffffu, s0, o);
        s1 += __shfl_down_sync(0xffffffffu, s1, o);
        s2 += __shfl_down_sync(0xffffffffu, s2, o);
        s3 += __shfl_down_sync(0xffffffffu, s3, o);
    }
    int wid = tid >> 5;
    if ((tid & 31) == 0){
        wred[wid][0]=s0; wred[wid][1]=s1; wred[wid][2]=s2; wred[wid][3]=s3;
    }
    __syncthreads();
    if (tid == 0){
        float t0=0,t1=0,t2=0,t3=0;
        #pragma unroll
        for (int w=0;w<8;w++){ t0+=wred[w][0]; t1+=wred[w][1]; t2+=wred[w][2]; t3+=wred[w][3]; }
        tot[0]=t0; tot[1]=t1; tot[2]=t2; tot[3]=t3;
    }
    __syncthreads();
    float mp = tot[0]*(1.0f/C_);
    float md = tot[3]*(1.0f/C_);
    if (tid < C_) g_pp[b*C_ + tid] = p - mp;
    if (tid == 0){
        g_sc[2*b]   = tot[1]*(1.0f/C_) - mp*mp;          // Vp
        g_sc[2*b+1] = tot[2]*(1.0f/C_) - mp*md;          // Cpd
    }
}

// ============================================================================
// K2: elementwise. out[b,c,n] = sigmoid(relu(ln(a*p+d))) * X[b,c,n]
// with closed-form LN stats.
// ============================================================================
__global__ __launch_bounds__(256, 4) void k2_kernel(
    const float* __restrict__ X,
    const float* __restrict__ b41, const float* __restrict__ w42,
    const float* __restrict__ b42, const float* __restrict__ ln_g,
    const float* __restrict__ ln_b, float* __restrict__ out)
{
    __shared__ float4 cdat[C_];          // {pp, dd, ln_g, ln_b} per channel
    __shared__ float wred[8][2];
    __shared__ float tot2[2];

    const int tid = threadIdx.x;
    const int b   = blockIdx.x;

    // d[c] (batch-independent) and its stats, computed deterministically
    float pp = 0.f, d = 0.f;
    if (tid < C_){
        pp = g_pp[b*C_ + tid];
        #pragma unroll
        for (int i=0;i<6;i++) d = fmaf(b41[i], w42[tid*6+i], d);
        d += b42[tid];
    }
    float s0 = d, s1 = d*d;
    #pragma unroll
    for (int o=16;o>0;o>>=1){
        s0 += __shfl_down_sync(0xffffffffu, s0, o);
        s1 += __shfl_down_sync(0xffffffffu, s1, o);
    }
    int wid = tid >> 5;
    if ((tid & 31) == 0){ wred[wid][0]=s0; wred[wid][1]=s1; }
    __syncthreads();
    if (tid == 0){
        float t0=0,t1=0;
        #pragma unroll
        for (int w=0;w<8;w++){ t0+=wred[w][0]; t1+=wred[w][1]; }
        tot2[0]=t0; tot2[1]=t1;
    }
    __syncthreads();
    float md = tot2[0]*(1.0f/C_);
    float Vd = tot2[1]*(1.0f/C_) - md*md;
    if (tid < C_) cdat[tid] = make_float4(pp, d - md, ln_g[tid], ln_b[tid]);
    __syncthreads();

    if (tid < HW_){
        float Vp  = g_sc[2*b];
        float Cpd = g_sc[2*b+1];
        float a   = g_kqs[b*HW_ + tid];
        // var = a^2*Vp + 2a*Cpd + Vd
        float var = fmaf(a, fmaf(a, Vp, 2.0f*Cpd), Vd) + 1e-5f;
        float rs  = rsqrtf(var);

        const float* xp = X   + (size_t)b*NELEM + tid;
        float*       op = out + (size_t)b*NELEM + tid;
        #pragma unroll 4
        for (int c=0;c<C_;c++){
            float  x  = xp[c*HW_];
            float4 cd = cdat[c];
            float t = fmaf(a, cd.x, cd.y) * rs;   // (x - mu)/sigma
            t = fmaf(t, cd.z, cd.w);              // * ln_g + ln_b
            t = fmaxf(t, 0.f);                    // relu
            float e    = __expf(-t);
            float gate = __fdividef(1.0f, 1.0f + e);  // sigmoid
            op[c*HW_] = gate * x;
        }
    }
}

// ============================================================================
extern "C" void kernel_launch(void* const* d_in, const int* in_sizes, int n_in,
                              void* d_out, int out_size)
{
    const float* X    = (const float*)d_in[0];
    const float* w11  = (const float*)d_in[1];
    const float* b11  = (const float*)d_in[2];
    const float* w21  = (const float*)d_in[3];
    const float* b21  = (const float*)d_in[4];
    const float* w31  = (const float*)d_in[5];
    const float* b31  = (const float*)d_in[6];
    const float* w41  = (const float*)d_in[7];
    const float* b41  = (const float*)d_in[8];
    const float* w42  = (const float*)d_in[9];
    const float* b42  = (const float*)d_in[10];
    const float* ln_g = (const float*)d_in[11];
    const float* ln_b = (const float*)d_in[12];
    float* out = (float*)d_out;

    k1_kernel<<<B_, 256>>>(X, w11,b11, w21,b21, w31,b31, w41,b41, w42,b42);
    k2_kernel<<<B_, 256>>>(X, b41, w42, b42, ln_g, ln_b, out);
}